// round 15
// baseline (speedup 1.0000x reference)
#include <cuda_runtime.h>
#include <cuda_bf16.h>
#include <math.h>
#include <stdint.h>

#define BATCH  4
#define NQ     4096
#define NC     1024
#define HEADS  8
#define DH     64
#define INNER  512
#define DX     512
#define DC     768

// ---------------- scratch (static device globals; no allocation) ----------
__device__ uint32_t g_xh[BATCH * NQ * DX / 2],  g_xl[BATCH * NQ * DX / 2];
__device__ uint32_t g_ch[BATCH * NC * DC / 2],  g_cl[BATCH * NC * DC / 2];
__device__ uint32_t g_Wqh[INNER * DX / 2],      g_Wql[INNER * DX / 2];   // [n][kp]
__device__ uint32_t g_Wkh[INNER * DC / 2],      g_Wkl[INNER * DC / 2];
__device__ uint32_t g_Wvh[INNER * DC / 2],      g_Wvl[INNER * DC / 2];
__device__ uint32_t g_Woh[INNER * INNER / 2],   g_Wol[INNER * INNER / 2];
__device__ uint32_t g_Qh[BATCH * HEADS * NQ * 32], g_Ql[BATCH * HEADS * NQ * 32];
__device__ uint32_t g_Kh[BATCH * HEADS * NC * 32], g_Kl[BATCH * HEADS * NC * 32];
__device__ uint32_t g_Vh[BATCH * HEADS * DH * NC / 2], g_Vl[BATCH * HEADS * DH * NC / 2];
__device__ uint32_t g_Ah[BATCH * NQ * 256], g_Al[BATCH * NQ * 256];

// ---------------------------------------------------------------------------
// helpers
// ---------------------------------------------------------------------------
__device__ __forceinline__ void mma16816(float c[4], uint32_t a0, uint32_t a1,
                                         uint32_t a2, uint32_t a3,
                                         uint32_t b0, uint32_t b1)
{
    asm volatile(
        "mma.sync.aligned.m16n8k16.row.col.f32.bf16.bf16.f32 "
        "{%0,%1,%2,%3},{%4,%5,%6,%7},{%8,%9},{%0,%1,%2,%3};"
        : "+f"(c[0]), "+f"(c[1]), "+f"(c[2]), "+f"(c[3])
        : "r"(a0), "r"(a1), "r"(a2), "r"(a3), "r"(b0), "r"(b1));
}

__device__ __forceinline__ uint32_t packbf(float lo, float hi)
{
    uint32_t r;
    asm("cvt.rn.bf16x2.f32 %0, %1, %2;" : "=r"(r) : "f"(hi), "f"(lo));
    return r;
}

__device__ __forceinline__ void split_pair(float v0, float v1,
                                           uint32_t& h, uint32_t& l)
{
    h = packbf(v0, v1);
    float h0 = __uint_as_float(h << 16);
    float h1 = __uint_as_float(h & 0xffff0000u);
    l = packbf(v0 - h0, v1 - h1);
}

__device__ __forceinline__ void cp16(uint32_t* s, const uint32_t* g)
{
    uint32_t sa = (uint32_t)__cvta_generic_to_shared(s);
    asm volatile("cp.async.cg.shared.global [%0], [%1], 16;"
                 :: "r"(sa), "l"(g) : "memory");
}
#define CP_COMMIT() asm volatile("cp.async.commit_group;" ::: "memory")
#define CP_WAIT1()  asm volatile("cp.async.wait_group 1;" ::: "memory")
#define CP_WAIT0()  asm volatile("cp.async.wait_group 0;" ::: "memory")

// ---------------------------------------------------------------------------
// single fused pre-conversion kernel (R12 proven)
// ---------------------------------------------------------------------------
__global__ __launch_bounds__(256)
void convert_all(const float* __restrict__ x, const float* __restrict__ ctx,
                 const float* __restrict__ Wq, const float* __restrict__ Wk,
                 const float* __restrict__ Wv, const float* __restrict__ Wo,
                 uint32_t* __restrict__ xh, uint32_t* __restrict__ xl,
                 uint32_t* __restrict__ ch, uint32_t* __restrict__ cl,
                 uint32_t* __restrict__ wqh, uint32_t* __restrict__ wql,
                 uint32_t* __restrict__ wkh, uint32_t* __restrict__ wkl,
                 uint32_t* __restrict__ wvh, uint32_t* __restrict__ wvl,
                 uint32_t* __restrict__ woh, uint32_t* __restrict__ wol)
{
    const int t = threadIdx.x;
    int bid = blockIdx.x;
    if (bid < 11264) {
        const float* src = (bid < 8192) ? x : ctx;
        uint32_t* h = (bid < 8192) ? xh : ch;
        uint32_t* l = (bid < 8192) ? xl : cl;
        int i = (bid < 8192 ? bid : bid - 8192) * 256 + t;
        float4 v = ((const float4*)src)[i];
        uint32_t h0, l0, h1, l1;
        split_pair(v.x, v.y, h0, l0);
        split_pair(v.z, v.w, h1, l1);
        ((uint2*)h)[i] = make_uint2(h0, h1);
        ((uint2*)l)[i] = make_uint2(l0, l1);
    } else {
        int e = bid - 11264;
        const float* W; uint32_t *th, *tl; int K;
        if (e < 512)       { W = Wq; th = wqh; tl = wql; K = DX; }
        else if (e < 1024) { e -= 512;  W = Wo; th = woh; tl = wol; K = INNER; }
        else if (e < 1792) { e -= 1024; W = Wk; th = wkh; tl = wkl; K = DC; }
        else               { e -= 1792; W = Wv; th = wvh; tl = wvl; K = DC; }
        int kp = e >> 1;
        int n  = (e & 1) * 256 + t;
        float w0 = W[(size_t)(2 * kp) * INNER + n];
        float w1 = W[(size_t)(2 * kp + 1) * INNER + n];
        uint32_t hh, ll;
        split_pair(w0, w1, hh, ll);
        th[(size_t)n * (K / 2) + kp] = hh;
        tl[(size_t)n * (K / 2) + kp] = ll;
    }
}

// ---------------------------------------------------------------------------
// cp.async double-buffered split-bf16 GEMM core. mma issue reordered: nf in
// pairs, terms interleaved -> same-acc RAW distance 4 (was 1).
// ---------------------------------------------------------------------------
__device__ __forceinline__ void gemm_core(
    const uint32_t* __restrict__ Ahg, const uint32_t* __restrict__ Alg,
    const uint32_t* __restrict__ Bhg, const uint32_t* __restrict__ Blg,
    uint32_t* smu, int Kp, int row0, int col0, float acc[2][8][4])
{
    const int t = threadIdx.x, lane = t & 31, w = t >> 5;
    const int wm = w & 3, wn = w >> 2;
    const int g = lane >> 2, qq = lane & 3;
    const int NT = Kp >> 4;

    auto stage = [&](int s, int kp0) {
        uint32_t* base = smu + s * 10240;
#pragma unroll
        for (int i = 0; i < 2; i++) {
            int e = t + 256 * i, r = e >> 2, c4 = (e & 3) * 4;
            size_t oa = (size_t)(row0 + r) * Kp + kp0 + c4;
            size_t ob = (size_t)(col0 + r) * Kp + kp0 + c4;
            cp16(base + r * 20 + c4,        Ahg + oa);
            cp16(base + 2560 + r * 20 + c4, Alg + oa);
            cp16(base + 5120 + r * 20 + c4, Bhg + ob);
            cp16(base + 7680 + r * 20 + c4, Blg + ob);
        }
        CP_COMMIT();
    };

    stage(0, 0);
    for (int it = 0; it < NT; it++) {
        int cur = it & 1;
        if (it + 1 < NT) { stage(cur ^ 1, (it + 1) * 16); CP_WAIT1(); }
        else             { CP_WAIT0(); }
        __syncthreads();
        uint32_t* Ahs = smu + cur * 10240;
        uint32_t* Als = Ahs + 2560;
        uint32_t* Bhs = Ahs + 5120;
        uint32_t* Bls = Ahs + 7680;
#pragma unroll
        for (int kk = 0; kk < 2; kk++) {
            const int c0 = 8 * kk + qq;
            uint32_t ah[2][4], al[2][4];
#pragma unroll
            for (int mf = 0; mf < 2; mf++) {
                int r = wm * 32 + 16 * mf + g;
                ah[mf][0] = Ahs[r * 20 + c0];     ah[mf][1] = Ahs[(r + 8) * 20 + c0];
                ah[mf][2] = Ahs[r * 20 + c0 + 4]; ah[mf][3] = Ahs[(r + 8) * 20 + c0 + 4];
                al[mf][0] = Als[r * 20 + c0];     al[mf][1] = Als[(r + 8) * 20 + c0];
                al[mf][2] = Als[r * 20 + c0 + 4]; al[mf][3] = Als[(r + 8) * 20 + c0 + 4];
            }
#pragma unroll
            for (int np = 0; np < 4; np++) {
                const int f0 = 2 * np, f1 = 2 * np + 1;
                const int n0 = wn * 64 + 8 * f0 + g;
                const int n1 = n0 + 8;
                uint32_t bh00 = Bhs[n0 * 20 + c0], bh01 = Bhs[n0 * 20 + c0 + 4];
                uint32_t bh10 = Bhs[n1 * 20 + c0], bh11 = Bhs[n1 * 20 + c0 + 4];
                uint32_t bl00 = Bls[n0 * 20 + c0], bl01 = Bls[n0 * 20 + c0 + 4];
                uint32_t bl10 = Bls[n1 * 20 + c0], bl11 = Bls[n1 * 20 + c0 + 4];
                // interleaved: same-acc mma are 4 apart; per-acc order
                // unchanged (h*bh, h*bl, l*bh) -> bit-identical result
                mma16816(acc[0][f0], ah[0][0], ah[0][1], ah[0][2], ah[0][3], bh00, bh01);
                mma16816(acc[1][f0], ah[1][0], ah[1][1], ah[1][2], ah[1][3], bh00, bh01);
                mma16816(acc[0][f1], ah[0][0], ah[0][1], ah[0][2], ah[0][3], bh10, bh11);
                mma16816(acc[1][f1], ah[1][0], ah[1][1], ah[1][2], ah[1][3], bh10, bh11);
                mma16816(acc[0][f0], ah[0][0], ah[0][1], ah[0][2], ah[0][3], bl00, bl01);
                mma16816(acc[1][f0], ah[1][0], ah[1][1], ah[1][2], ah[1][3], bl00, bl01);
                mma16816(acc[0][f1], ah[0][0], ah[0][1], ah[0][2], ah[0][3], bl10, bl11);
                mma16816(acc[1][f1], ah[1][0], ah[1][1], ah[1][2], ah[1][3], bl10, bl11);
                mma16816(acc[0][f0], al[0][0], al[0][1], al[0][2], al[0][3], bh00, bh01);
                mma16816(acc[1][f0], al[1][0], al[1][1], al[1][2], al[1][3], bh00, bh01);
                mma16816(acc[0][f1], al[0][0], al[0][1], al[0][2], al[0][3], bh10, bh11);
                mma16816(acc[1][f1], al[1][0], al[1][1], al[1][2], al[1][3], bh10, bh11);
            }
        }
        __syncthreads();
    }
}

// ---------------------------------------------------------------------------
// fused QKV projection (R12 proven epilogues)
// ---------------------------------------------------------------------------
__global__ __launch_bounds__(256, 2)
void proj_all(const uint32_t* __restrict__ xh, const uint32_t* __restrict__ xl,
              const uint32_t* __restrict__ ch, const uint32_t* __restrict__ cl,
              const uint32_t* __restrict__ wqh, const uint32_t* __restrict__ wql,
              const uint32_t* __restrict__ wkh, const uint32_t* __restrict__ wkl,
              const uint32_t* __restrict__ wvh, const uint32_t* __restrict__ wvl,
              uint32_t* __restrict__ qh, uint32_t* __restrict__ ql,
              uint32_t* __restrict__ kh, uint32_t* __restrict__ kl,
              uint32_t* __restrict__ vh, uint32_t* __restrict__ vl)
{
    extern __shared__ uint32_t smu[];
    const int bid = blockIdx.x;
    const bool isQ = bid < 512;
    const int e2 = isQ ? bid : ((bid - 512) & 127);
    const bool isV = !isQ && (bid - 512) >= 128;
    const int row0 = (e2 >> 2) * 128, col0 = (e2 & 3) * 128;
    const int K   = isQ ? DX : DC;
    const int SEQ = isQ ? NQ : NC;
    const uint32_t* Ahg = isQ ? xh : ch;
    const uint32_t* Alg = isQ ? xl : cl;
    const uint32_t* Bhg = isQ ? wqh : (isV ? wvh : wkh);
    const uint32_t* Blg = isQ ? wql : (isV ? wvl : wkl);

    const int t = threadIdx.x, lane = t & 31, w = t >> 5;
    const int wm = w & 3, wn = w >> 2;
    const int g = lane >> 2, qq = lane & 3;

    float acc[2][8][4];
#pragma unroll
    for (int mf = 0; mf < 2; mf++)
#pragma unroll
        for (int nf = 0; nf < 8; nf++)
#pragma unroll
            for (int r = 0; r < 4; r++) acc[mf][nf][r] = 0.0f;

    gemm_core(Ahg, Alg, Bhg, Blg, smu, K >> 1, row0, col0, acc);

    const float scale = isQ ? 0.125f : 1.0f;
    uint32_t* Ph = isQ ? qh : (isV ? vh : kh);
    uint32_t* Pl = isQ ? ql : (isV ? vl : kl);

#pragma unroll
    for (int mf = 0; mf < 2; mf++) {
#pragma unroll
        for (int nf = 0; nf < 8; nf++) {
            int m = row0 + wm * 32 + 16 * mf + g;
            int n = col0 + wn * 64 + 8 * nf + 2 * qq;
            float* c = acc[mf][nf];
            int hh_ = n >> 6, d = n & 63;
            int bb = m / SEQ, s = m - bb * SEQ;
            if (!isV) {
                size_t base = ((size_t)(bb * HEADS + hh_) * SEQ + s) * 32 + (d >> 1);
                uint32_t ph, pl;
                split_pair(c[0] * scale, c[1] * scale, ph, pl);
                Ph[base] = ph; Pl[base] = pl;
                split_pair(c[2] * scale, c[3] * scale, ph, pl);
                Ph[base + 8 * 32] = ph; Pl[base + 8 * 32] = pl;
            } else {
                __nv_bfloat16* Vh = (__nv_bfloat16*)Ph;
                __nv_bfloat16* Vl = (__nv_bfloat16*)Pl;
                size_t vb = ((size_t)(bb * HEADS + hh_) * DH + d) * NC + s;
#pragma unroll
                for (int r = 0; r < 4; r++) {
                    size_t a = vb + (size_t)(r & 1) * NC + (r >> 1) * 8;
                    __nv_bfloat16 bh = __float2bfloat16(c[r]);
                    Vh[a] = bh;
                    Vl[a] = __float2bfloat16(c[r] - __bfloat162float(bh));
                }
            }
        }
    }
}

// ---------------------------------------------------------------------------
// output GEMM: fp32 + bias
// ---------------------------------------------------------------------------
__global__ __launch_bounds__(256, 2)
void hgemm_out(const uint32_t* __restrict__ Ahg, const uint32_t* __restrict__ Alg,
               const uint32_t* __restrict__ Bhg, const uint32_t* __restrict__ Blg,
               float* __restrict__ C, int K, const float* __restrict__ bias)
{
    extern __shared__ uint32_t smu[];
    const int t = threadIdx.x, lane = t & 31, w = t >> 5;
    const int wm = w & 3, wn = w >> 2;
    const int g = lane >> 2, qq = lane & 3;
    const int row0 = blockIdx.y * 128, col0 = blockIdx.x * 128;

    float acc[2][8][4];
#pragma unroll
    for (int mf = 0; mf < 2; mf++)
#pragma unroll
        for (int nf = 0; nf < 8; nf++)
#pragma unroll
            for (int r = 0; r < 4; r++) acc[mf][nf][r] = 0.0f;

    gemm_core(Ahg, Alg, Bhg, Blg, smu, K >> 1, row0, col0, acc);

#pragma unroll
    for (int mf = 0; mf < 2; mf++) {
#pragma unroll
        for (int nf = 0; nf < 8; nf++) {
            int m = row0 + wm * 32 + 16 * mf + g;
            int n = col0 + wn * 64 + 8 * nf + 2 * qq;
            float* c = acc[mf][nf];
            float2 bv = *(const float2*)&bias[n];
            *(float2*)&C[(size_t)m * INNER + n] =
                make_float2(c[0] + bv.x, c[1] + bv.y);
            *(float2*)&C[(size_t)(m + 8) * INNER + n] =
                make_float2(c[2] + bv.x, c[3] + bv.y);
        }
    }
}

// ---------------------------------------------------------------------------
// Tensor-core attention: cp.async double-buffered K/V, fused exp+PV.
// mma reordered in j-pairs (same-acc RAW distance 2, was 1).
// ---------------------------------------------------------------------------
__global__ __launch_bounds__(256, 2)
void attn_mma3(const uint32_t* __restrict__ Qhg, const uint32_t* __restrict__ Qlg,
               const uint32_t* __restrict__ Khg, const uint32_t* __restrict__ Klg,
               const uint32_t* __restrict__ Vhg, const uint32_t* __restrict__ Vlg,
               uint32_t* __restrict__ Ah, uint32_t* __restrict__ Al)
{
    extern __shared__ uint32_t sm[];
    uint32_t* Qh = sm;              // 128 x 36
    uint32_t* Ql = sm + 4608;

    const int t = threadIdx.x, lane = t & 31, w = t >> 5;
    const int g  = lane >> 2;
    const int qq = lane & 3;
    const int q0 = blockIdx.x * 128;
    const int h  = blockIdx.y;
    const int b  = blockIdx.z;

    const size_t qbase = ((size_t)(b * HEADS + h) * NQ + q0) * 32;
    const size_t kbase = (size_t)(b * HEADS + h) * NC * 32;
    const size_t vbase = (size_t)(b * HEADS + h) * DH * 512;

    auto stageKV = [&](int s, int kt) {
        uint32_t* base = sm + 9216 + s * 9216;
#pragma unroll
        for (int i = 0; i < 2; i++) {
            int e = t + 256 * i, r = e >> 3, c4 = (e & 7) * 4;
            size_t ok = kbase + (size_t)(kt * 64 + r) * 32 + c4;
            size_t ov = vbase + (size_t)r * 512 + kt * 32 + c4;
            cp16(base + r * 36 + c4,        Khg + ok);
            cp16(base + 2304 + r * 36 + c4, Klg + ok);
            cp16(base + 4608 + r * 36 + c4, Vhg + ov);
            cp16(base + 6912 + r * 36 + c4, Vlg + ov);
        }
        CP_COMMIT();
    };

    stageKV(0, 0);

#pragma unroll
    for (int i = 0; i < 4; i++) {
        int e = t + 256 * i;
        int r = e >> 3, c4 = (e & 7) * 4;
        *(uint4*)&Qh[r * 36 + c4] = *(const uint4*)&Qhg[qbase + (size_t)r * 32 + c4];
        *(uint4*)&Ql[r * 36 + c4] = *(const uint4*)&Qlg[qbase + (size_t)r * 32 + c4];
    }

    float o[8][4];
    float rs[2] = {0.f, 0.f};
#pragma unroll
    for (int j = 0; j < 8; j++)
#pragma unroll
        for (int r = 0; r < 4; r++) o[j][r] = 0.f;

    const int r0 = 16 * w + g;

    for (int kt = 0; kt < NC / 64; kt++) {
        int cur = kt & 1;
        if (kt + 1 < NC / 64) { stageKV(cur ^ 1, kt + 1); CP_WAIT1(); }
        else                  { CP_WAIT0(); }
        __syncthreads();
        uint32_t* Kh = sm + 9216 + cur * 9216;
        uint32_t* Kl = Kh + 2304;
        uint32_t* Vh = Kh + 4608;
        uint32_t* Vl = Kh + 6912;

        float s[8][4];
#pragma unroll
        for (int j = 0; j < 8; j++)
#pragma unroll
            for (int r = 0; r < 4; r++) s[j][r] = 0.f;

#pragma unroll
        for (int kk = 0; kk < 4; kk++) {
            int c0 = qq + 8 * kk;
            uint32_t qh0 = Qh[r0 * 36 + c0],       qh1 = Qh[(r0 + 8) * 36 + c0];
            uint32_t qh2 = Qh[r0 * 36 + c0 + 4],   qh3 = Qh[(r0 + 8) * 36 + c0 + 4];
            uint32_t ql0 = Ql[r0 * 36 + c0],       ql1 = Ql[(r0 + 8) * 36 + c0];
            uint32_t ql2 = Ql[r0 * 36 + c0 + 4],   ql3 = Ql[(r0 + 8) * 36 + c0 + 4];
#pragma unroll
            for (int jp = 0; jp < 4; jp++) {
                const int j0 = 2 * jp, j1 = 2 * jp + 1;
                const int k0 = 8 * j0 + g, k1 = 8 * j1 + g;
                uint32_t kh00 = Kh[k0 * 36 + c0], kh01 = Kh[k0 * 36 + c0 + 4];
                uint32_t kh10 = Kh[k1 * 36 + c0], kh11 = Kh[k1 * 36 + c0 + 4];
                uint32_t kl00 = Kl[k0 * 36 + c0], kl01 = Kl[k0 * 36 + c0 + 4];
                uint32_t kl10 = Kl[k1 * 36 + c0], kl11 = Kl[k1 * 36 + c0 + 4];
                mma16816(s[j0], qh0, qh1, qh2, qh3, kh00, kh01);
                mma16816(s[j1], qh0, qh1, qh2, qh3, kh10, kh11);
                mma16816(s[j0], qh0, qh1, qh2, qh3, kl00, kl01);
                mma16816(s[j1], qh0, qh1, qh2, qh3, kl10, kl11);
                mma16816(s[j0], ql0, ql1, ql2, ql3, kh00, kh01);
                mma16816(s[j1], ql0, ql1, ql2, ql3, kh10, kh11);
            }
        }

#pragma unroll
        for (int kk = 0; kk < 4; kk++) {
            uint32_t a0, a1, a2, a3, l0, l1, l2, l3;
            {
                float* sj = s[2 * kk];
                float e0 = __expf(sj[0]), e1 = __expf(sj[1]);
                float e2 = __expf(sj[2]), e3 = __expf(sj[3]);
                rs[0] += e0 + e1; rs[1] += e2 + e3;
                split_pair(e0, e1, a0, l0);
                split_pair(e2, e3, a1, l1);
            }
            {
                float* sj = s[2 * kk + 1];
                float e0 = __expf(sj[0]), e1 = __expf(sj[1]);
                float e2 = __expf(sj[2]), e3 = __expf(sj[3]);
                rs[0] += e0 + e1; rs[1] += e2 + e3;
                split_pair(e0, e1, a2, l2);
                split_pair(e2, e3, a3, l3);
            }
            int cp = qq + 8 * kk;
#pragma unroll
            for (int jp = 0; jp < 4; jp++) {
                const int j0 = 2 * jp, j1 = 2 * jp + 1;
                const int d0 = 8 * j0 + g, d1 = 8 * j1 + g;
                uint32_t vh00 = Vh[d0 * 36 + cp], vh01 = Vh[d0 * 36 + cp + 4];
                uint32_t vh10 = Vh[d1 * 36 + cp], vh11 = Vh[d1 * 36 + cp + 4];
                uint32_t vl00 = Vl[d0 * 36 + cp], vl01 = Vl[d0 * 36 + cp + 4];
                uint32_t vl10 = Vl[d1 * 36 + cp], vl11 = Vl[d1 * 36 + cp + 4];
                mma16816(o[j0], a0, a1, a2, a3, vh00, vh01);
                mma16816(o[j1], a0, a1, a2, a3, vh10, vh11);
                mma16816(o[j0], a0, a1, a2, a3, vl00, vl01);
                mma16816(o[j1], a0, a1, a2, a3, vl10, vl11);
                mma16816(o[j0], l0, l1, l2, l3, vh00, vh01);
                mma16816(o[j1], l0, l1, l2, l3, vh10, vh11);
            }
        }
        __syncthreads();
    }

    rs[0] += __shfl_xor_sync(0xffffffffu, rs[0], 1);
    rs[0] += __shfl_xor_sync(0xffffffffu, rs[0], 2);
    rs[1] += __shfl_xor_sync(0xffffffffu, rs[1], 1);
    rs[1] += __shfl_xor_sync(0xffffffffu, rs[1], 2);
    float inv0 = 1.0f / rs[0], inv1 = 1.0f / rs[1];

#pragma unroll
    for (int j = 0; j < 8; j++) {
        uint32_t hh, ll;
        size_t r1 = (size_t)(b * NQ + q0 + 16 * w + g) * 256 + h * 32 + 4 * j + qq;
        split_pair(o[j][0] * inv0, o[j][1] * inv0, hh, ll);
        Ah[r1] = hh; Al[r1] = ll;
        split_pair(o[j][2] * inv1, o[j][3] * inv1, hh, ll);
        Ah[r1 + 8 * 256] = hh; Al[r1 + 8 * 256] = ll;
    }
}

// ---------------------------------------------------------------------------
extern "C" void kernel_launch(void* const* d_in, const int* in_sizes, int n_in,
                              void* d_out, int out_size)
{
    const float* x   = (const float*)d_in[0];
    const float* ctx = (const float*)d_in[1];
    const float* Wq  = (const float*)d_in[2];
    const float* Wk  = (const float*)d_in[3];
    const float* Wv  = (const float*)d_in[4];
    const float* Wo  = (const float*)d_in[5];
    const float* bo  = (const float*)d_in[6];
    float* out = (float*)d_out;

    uint32_t *xh, *xl, *ch, *cl, *wqh, *wql, *wkh, *wkl, *wvh, *wvl, *woh, *wol;
    uint32_t *qh, *ql, *kh, *kl, *vh, *vl, *ah, *al;
    cudaGetSymbolAddress((void**)&xh, g_xh);   cudaGetSymbolAddress((void**)&xl, g_xl);
    cudaGetSymbolAddress((void**)&ch, g_ch);   cudaGetSymbolAddress((void**)&cl, g_cl);
    cudaGetSymbolAddress((void**)&wqh, g_Wqh); cudaGetSymbolAddress((void**)&wql, g_Wql);
    cudaGetSymbolAddress((void**)&wkh, g_Wkh); cudaGetSymbolAddress((void**)&wkl, g_Wkl);
    cudaGetSymbolAddress((void**)&wvh, g_Wvh); cudaGetSymbolAddress((void**)&wvl, g_Wvl);
    cudaGetSymbolAddress((void**)&woh, g_Woh); cudaGetSymbolAddress((void**)&wol, g_Wol);
    cudaGetSymbolAddress((void**)&qh, g_Qh);   cudaGetSymbolAddress((void**)&ql, g_Ql);
    cudaGetSymbolAddress((void**)&kh, g_Kh);   cudaGetSymbolAddress((void**)&kl, g_Kl);
    cudaGetSymbolAddress((void**)&vh, g_Vh);   cudaGetSymbolAddress((void**)&vl, g_Vl);
    cudaGetSymbolAddress((void**)&ah, g_Ah);   cudaGetSymbolAddress((void**)&al, g_Al);

    cudaFuncSetAttribute(attn_mma3,
                         cudaFuncAttributeMaxDynamicSharedMemorySize, 110592);
    cudaFuncSetAttribute(proj_all,
                         cudaFuncAttributeMaxDynamicSharedMemorySize, 81920);
    cudaFuncSetAttribute(hgemm_out,
                         cudaFuncAttributeMaxDynamicSharedMemorySize, 81920);

    dim3 blk(256);

    convert_all<<<13824, blk>>>(x, ctx, Wq, Wk, Wv, Wo,
                                xh, xl, ch, cl, wqh, wql, wkh, wkl,
                                wvh, wvl, woh, wol);

    proj_all<<<768, blk, 81920>>>(xh, xl, ch, cl, wqh, wql, wkh, wkl,
                                  wvh, wvl, qh, ql, kh, kl, vh, vl);

    attn_mma3<<<dim3(NQ / 128, HEADS, BATCH), blk, 110592>>>(
        qh, ql, kh, kl, vh, vl, ah, al);

    hgemm_out<<<dim3(4, (BATCH * NQ) / 128), blk, 81920>>>(
        ah, al, woh, wol, out, INNER, bo);

    (void)in_sizes; (void)n_in; (void)out_size;
}

// round 17
// speedup vs baseline: 1.4275x; 1.4275x over previous
#include <cuda_runtime.h>
#include <cuda_fp16.h>
#include <math.h>
#include <stdint.h>

#define BATCH  4
#define NQ     4096
#define NC     1024
#define HEADS  8
#define DH     64
#define INNER  512
#define DX     512
#define DC     768

// ---------------- scratch (static device globals; no allocation) ----------
// fp16 pair arrays (u32 = 2 half, low half = even index)
__device__ uint32_t g_xh[BATCH * NQ * DX / 2],  g_xl[BATCH * NQ * DX / 2];
__device__ uint32_t g_ch[BATCH * NC * DC / 2],  g_cl[BATCH * NC * DC / 2];
__device__ uint32_t g_Wqh[INNER * DX / 2];            // [n][kp], high only
__device__ uint32_t g_Wkh[INNER * DC / 2];
__device__ uint32_t g_Wvh[INNER * DC / 2];
__device__ uint32_t g_Woh[INNER * INNER / 2];
__device__ uint32_t g_Qh[BATCH * HEADS * NQ * 32], g_Ql[BATCH * HEADS * NQ * 32];
__device__ uint32_t g_Kh[BATCH * HEADS * NC * 32];                 // high only
__device__ uint32_t g_Vh[BATCH * HEADS * DH * NC / 2];             // V^T high
__device__ uint32_t g_Ah[BATCH * NQ * 256], g_Al[BATCH * NQ * 256];

// ---------------------------------------------------------------------------
// helpers (fp16 mma, fp16 split)
// ---------------------------------------------------------------------------
__device__ __forceinline__ void mma16816(float c[4], uint32_t a0, uint32_t a1,
                                         uint32_t a2, uint32_t a3,
                                         uint32_t b0, uint32_t b1)
{
    asm volatile(
        "mma.sync.aligned.m16n8k16.row.col.f32.f16.f16.f32 "
        "{%0,%1,%2,%3},{%4,%5,%6,%7},{%8,%9},{%0,%1,%2,%3};"
        : "+f"(c[0]), "+f"(c[1]), "+f"(c[2]), "+f"(c[3])
        : "r"(a0), "r"(a1), "r"(a2), "r"(a3), "r"(b0), "r"(b1));
}

// pack (lo, hi) floats into f16x2; lo in low 16 bits
__device__ __forceinline__ uint32_t packh(float lo, float hi)
{
    uint32_t r;
    asm("cvt.rn.f16x2.f32 %0, %1, %2;" : "=r"(r) : "f"(hi), "f"(lo));
    return r;
}

__device__ __forceinline__ void split_pair(float v0, float v1,
                                           uint32_t& h, uint32_t& l)
{
    h = packh(v0, v1);
    float h0 = __half2float(__ushort_as_half((unsigned short)(h & 0xffffu)));
    float h1 = __half2float(__ushort_as_half((unsigned short)(h >> 16)));
    l = packh(v0 - h0, v1 - h1);
}

__device__ __forceinline__ void cp16(uint32_t* s, const uint32_t* g)
{
    uint32_t sa = (uint32_t)__cvta_generic_to_shared(s);
    asm volatile("cp.async.cg.shared.global [%0], [%1], 16;"
                 :: "r"(sa), "l"(g) : "memory");
}
#define CP_COMMIT() asm volatile("cp.async.commit_group;" ::: "memory")
#define CP_WAIT1()  asm volatile("cp.async.wait_group 1;" ::: "memory")
#define CP_WAIT0()  asm volatile("cp.async.wait_group 0;" ::: "memory")

// ---------------------------------------------------------------------------
// fused pre-conversion: x/ctx split pairs + 4 weights (high only, transposed)
// grid: [0,8192) x | [8192,11264) ctx | [11264,13824) weights
// ---------------------------------------------------------------------------
__global__ __launch_bounds__(256)
void convert_all(const float* __restrict__ x, const float* __restrict__ ctx,
                 const float* __restrict__ Wq, const float* __restrict__ Wk,
                 const float* __restrict__ Wv, const float* __restrict__ Wo,
                 uint32_t* __restrict__ xh, uint32_t* __restrict__ xl,
                 uint32_t* __restrict__ ch, uint32_t* __restrict__ cl,
                 uint32_t* __restrict__ wqh, uint32_t* __restrict__ wkh,
                 uint32_t* __restrict__ wvh, uint32_t* __restrict__ woh)
{
    const int t = threadIdx.x;
    int bid = blockIdx.x;
    if (bid < 11264) {
        const float* src = (bid < 8192) ? x : ctx;
        uint32_t* h = (bid < 8192) ? xh : ch;
        uint32_t* l = (bid < 8192) ? xl : cl;
        int i = (bid < 8192 ? bid : bid - 8192) * 256 + t;
        float4 v = ((const float4*)src)[i];
        uint32_t h0, l0, h1, l1;
        split_pair(v.x, v.y, h0, l0);
        split_pair(v.z, v.w, h1, l1);
        ((uint2*)h)[i] = make_uint2(h0, h1);
        ((uint2*)l)[i] = make_uint2(l0, l1);
    } else {
        int e = bid - 11264;
        const float* W; uint32_t* th; int K;
        if (e < 512)       { W = Wq; th = wqh; K = DX; }
        else if (e < 1024) { e -= 512;  W = Wo; th = woh; K = INNER; }
        else if (e < 1792) { e -= 1024; W = Wk; th = wkh; K = DC; }
        else               { e -= 1792; W = Wv; th = wvh; K = DC; }
        int kp = e >> 1;
        int n  = (e & 1) * 256 + t;
        float w0 = W[(size_t)(2 * kp) * INNER + n];
        float w1 = W[(size_t)(2 * kp + 1) * INNER + n];
        th[(size_t)n * (K / 2) + kp] = packh(w0, w1);
    }
}

// ---------------------------------------------------------------------------
// cp.async double-buffered 2-mma fp16 GEMM core.
// smem per stage: Ah 2560 | Al 2560 | Bh 2560 u32 (30 KB), 2 stages = 60 KB.
// stage tile: 3 arrays x 128 rows x 4 float4 chunks = 1536 cp16 entries.
// ---------------------------------------------------------------------------
__device__ __forceinline__ void gemm_core(
    const uint32_t* __restrict__ Ahg, const uint32_t* __restrict__ Alg,
    const uint32_t* __restrict__ Bhg,
    uint32_t* smu, int Kp, int row0, int col0, float acc[2][8][4])
{
    const int t = threadIdx.x, lane = t & 31, w = t >> 5;
    const int wm = w & 3, wn = w >> 2;
    const int g = lane >> 2, qq = lane & 3;
    const int NT = Kp >> 4;

    auto stage = [&](int s, int kp0) {
        uint32_t* base = smu + s * 7680;
#pragma unroll
        for (int i = 0; i < 6; i++) {
            int e = t + 256 * i;             // e in [0, 1536)
            int arr = e >> 9;                // /512 -> 0,1,2
            int e2 = e & 511;
            int r = e2 >> 2, c4 = (e2 & 3) * 4;
            const uint32_t* gsrc = (arr == 0) ? Ahg : (arr == 1) ? Alg : Bhg;
            int rb = (arr < 2) ? row0 : col0;
            cp16(base + arr * 2560 + r * 20 + c4,
                 gsrc + (size_t)(rb + r) * Kp + kp0 + c4);
        }
        CP_COMMIT();
    };

    stage(0, 0);
    for (int it = 0; it < NT; it++) {
        int cur = it & 1;
        if (it + 1 < NT) { stage(cur ^ 1, (it + 1) * 16); CP_WAIT1(); }
        else             { CP_WAIT0(); }
        __syncthreads();
        uint32_t* Ahs = smu + cur * 7680;
        uint32_t* Als = Ahs + 2560;
        uint32_t* Bhs = Ahs + 5120;
#pragma unroll
        for (int kk = 0; kk < 2; kk++) {
            const int c0 = 8 * kk + qq;
            uint32_t ah[2][4], al[2][4];
#pragma unroll
            for (int mf = 0; mf < 2; mf++) {
                int r = wm * 32 + 16 * mf + g;
                ah[mf][0] = Ahs[r * 20 + c0];     ah[mf][1] = Ahs[(r + 8) * 20 + c0];
                ah[mf][2] = Ahs[r * 20 + c0 + 4]; ah[mf][3] = Ahs[(r + 8) * 20 + c0 + 4];
                al[mf][0] = Als[r * 20 + c0];     al[mf][1] = Als[(r + 8) * 20 + c0];
                al[mf][2] = Als[r * 20 + c0 + 4]; al[mf][3] = Als[(r + 8) * 20 + c0 + 4];
            }
#pragma unroll
            for (int nf = 0; nf < 8; nf++) {
                int n = wn * 64 + 8 * nf + g;
                uint32_t bh0 = Bhs[n * 20 + c0], bh1 = Bhs[n * 20 + c0 + 4];
                mma16816(acc[0][nf], ah[0][0], ah[0][1], ah[0][2], ah[0][3], bh0, bh1);
                mma16816(acc[1][nf], ah[1][0], ah[1][1], ah[1][2], ah[1][3], bh0, bh1);
                mma16816(acc[0][nf], al[0][0], al[0][1], al[0][2], al[0][3], bh0, bh1);
                mma16816(acc[1][nf], al[1][0], al[1][1], al[1][2], al[1][3], bh0, bh1);
            }
        }
        __syncthreads();
    }
}

// ---------------------------------------------------------------------------
// fused QKV projection: bid<512 Q (pairs, scale 1/8) | [512,640) K (high) |
// [640,768) V (V^T high)
// ---------------------------------------------------------------------------
__global__ __launch_bounds__(256, 2)
void proj_all(const uint32_t* __restrict__ xh, const uint32_t* __restrict__ xl,
              const uint32_t* __restrict__ ch, const uint32_t* __restrict__ cl,
              const uint32_t* __restrict__ wqh, const uint32_t* __restrict__ wkh,
              const uint32_t* __restrict__ wvh,
              uint32_t* __restrict__ qh, uint32_t* __restrict__ ql,
              uint32_t* __restrict__ kh, uint32_t* __restrict__ vh)
{
    extern __shared__ uint32_t smu[];
    const int bid = blockIdx.x;
    const bool isQ = bid < 512;
    const int e2 = isQ ? bid : ((bid - 512) & 127);
    const bool isV = !isQ && (bid - 512) >= 128;
    const int row0 = (e2 >> 2) * 128, col0 = (e2 & 3) * 128;
    const int K   = isQ ? DX : DC;
    const int SEQ = isQ ? NQ : NC;
    const uint32_t* Ahg = isQ ? xh : ch;
    const uint32_t* Alg = isQ ? xl : cl;
    const uint32_t* Bhg = isQ ? wqh : (isV ? wvh : wkh);

    const int t = threadIdx.x, lane = t & 31, w = t >> 5;
    const int wm = w & 3, wn = w >> 2;
    const int g = lane >> 2, qq = lane & 3;

    float acc[2][8][4];
#pragma unroll
    for (int mf = 0; mf < 2; mf++)
#pragma unroll
        for (int nf = 0; nf < 8; nf++)
#pragma unroll
            for (int r = 0; r < 4; r++) acc[mf][nf][r] = 0.0f;

    gemm_core(Ahg, Alg, Bhg, smu, K >> 1, row0, col0, acc);

#pragma unroll
    for (int mf = 0; mf < 2; mf++) {
#pragma unroll
        for (int nf = 0; nf < 8; nf++) {
            int m = row0 + wm * 32 + 16 * mf + g;
            int n = col0 + wn * 64 + 8 * nf + 2 * qq;
            float* c = acc[mf][nf];
            int hh_ = n >> 6, d = n & 63;
            int bb = m / SEQ, s = m - bb * SEQ;
            if (isQ) {
                size_t base = ((size_t)(bb * HEADS + hh_) * SEQ + s) * 32 + (d >> 1);
                uint32_t ph, pl;
                split_pair(c[0] * 0.125f, c[1] * 0.125f, ph, pl);
                qh[base] = ph; ql[base] = pl;
                split_pair(c[2] * 0.125f, c[3] * 0.125f, ph, pl);
                qh[base + 8 * 32] = ph; ql[base + 8 * 32] = pl;
            } else if (!isV) {
                size_t base = ((size_t)(bb * HEADS + hh_) * NC + s) * 32 + (d >> 1);
                kh[base]          = packh(c[0], c[1]);
                kh[base + 8 * 32] = packh(c[2], c[3]);
            } else {
                __half* Vp = (__half*)vh;
                size_t vb = ((size_t)(bb * HEADS + hh_) * DH + d) * NC + s;
#pragma unroll
                for (int r = 0; r < 4; r++) {
                    size_t a = vb + (size_t)(r & 1) * NC + (r >> 1) * 8;
                    Vp[a] = __float2half(c[r]);
                }
            }
        }
    }
}

// ---------------------------------------------------------------------------
// output GEMM: fp32 + bias
// ---------------------------------------------------------------------------
__global__ __launch_bounds__(256, 2)
void hgemm_out(const uint32_t* __restrict__ Ahg, const uint32_t* __restrict__ Alg,
               const uint32_t* __restrict__ Bhg,
               float* __restrict__ C, int K, const float* __restrict__ bias)
{
    extern __shared__ uint32_t smu[];
    const int t = threadIdx.x, lane = t & 31, w = t >> 5;
    const int wm = w & 3, wn = w >> 2;
    const int g = lane >> 2, qq = lane & 3;
    const int row0 = blockIdx.y * 128, col0 = blockIdx.x * 128;

    float acc[2][8][4];
#pragma unroll
    for (int mf = 0; mf < 2; mf++)
#pragma unroll
        for (int nf = 0; nf < 8; nf++)
#pragma unroll
            for (int r = 0; r < 4; r++) acc[mf][nf][r] = 0.0f;

    gemm_core(Ahg, Alg, Bhg, smu, K >> 1, row0, col0, acc);

#pragma unroll
    for (int mf = 0; mf < 2; mf++) {
#pragma unroll
        for (int nf = 0; nf < 8; nf++) {
            int m = row0 + wm * 32 + 16 * mf + g;
            int n = col0 + wn * 64 + 8 * nf + 2 * qq;
            float* c = acc[mf][nf];
            float2 bv = *(const float2*)&bias[n];
            *(float2*)&C[(size_t)m * INNER + n] =
                make_float2(c[0] + bv.x, c[1] + bv.y);
            *(float2*)&C[(size_t)(m + 8) * INNER + n] =
                make_float2(c[2] + bv.x, c[3] + bv.y);
        }
    }
}

// ---------------------------------------------------------------------------
// Attention: 2-mma fp16 (Q split / K high; P split / V high), double-buffered
// K/V (18 KB/stage), fused exp+PV. Dyn smem 73728 B, 2 CTAs/SM.
// ---------------------------------------------------------------------------
__global__ __launch_bounds__(256, 2)
void attn_mma3(const uint32_t* __restrict__ Qhg, const uint32_t* __restrict__ Qlg,
               const uint32_t* __restrict__ Khg, const uint32_t* __restrict__ Vhg,
               uint32_t* __restrict__ Ah, uint32_t* __restrict__ Al)
{
    extern __shared__ uint32_t sm[];
    uint32_t* Qh = sm;              // 128 x 36
    uint32_t* Ql = sm + 4608;

    const int t = threadIdx.x, lane = t & 31, w = t >> 5;
    const int g  = lane >> 2;
    const int qq = lane & 3;
    const int q0 = blockIdx.x * 128;
    const int h  = blockIdx.y;
    const int b  = blockIdx.z;

    const size_t qbase = ((size_t)(b * HEADS + h) * NQ + q0) * 32;
    const size_t kbase = (size_t)(b * HEADS + h) * NC * 32;
    const size_t vbase = (size_t)(b * HEADS + h) * DH * 512;

    auto stageKV = [&](int s, int kt) {
        uint32_t* base = sm + 9216 + s * 4608;   // Kh 2304 | Vh 2304
#pragma unroll
        for (int i = 0; i < 2; i++) {
            int e = t + 256 * i, r = e >> 3, c4 = (e & 7) * 4;
            cp16(base + r * 36 + c4,        Khg + kbase + (size_t)(kt * 64 + r) * 32 + c4);
            cp16(base + 2304 + r * 36 + c4, Vhg + vbase + (size_t)r * 512 + kt * 32 + c4);
        }
        CP_COMMIT();
    };

    stageKV(0, 0);

#pragma unroll
    for (int i = 0; i < 4; i++) {
        int e = t + 256 * i;
        int r = e >> 3, c4 = (e & 7) * 4;
        *(uint4*)&Qh[r * 36 + c4] = *(const uint4*)&Qhg[qbase + (size_t)r * 32 + c4];
        *(uint4*)&Ql[r * 36 + c4] = *(const uint4*)&Qlg[qbase + (size_t)r * 32 + c4];
    }

    float o[8][4];
    float rs[2] = {0.f, 0.f};
#pragma unroll
    for (int j = 0; j < 8; j++)
#pragma unroll
        for (int r = 0; r < 4; r++) o[j][r] = 0.f;

    const int r0 = 16 * w + g;

    for (int kt = 0; kt < NC / 64; kt++) {
        int cur = kt & 1;
        if (kt + 1 < NC / 64) { stageKV(cur ^ 1, kt + 1); CP_WAIT1(); }
        else                  { CP_WAIT0(); }
        __syncthreads();
        uint32_t* Kh = sm + 9216 + cur * 4608;
        uint32_t* Vh = Kh + 2304;

        float s[8][4];
#pragma unroll
        for (int j = 0; j < 8; j++)
#pragma unroll
            for (int r = 0; r < 4; r++) s[j][r] = 0.f;

#pragma unroll
        for (int kk = 0; kk < 4; kk++) {
            int c0 = qq + 8 * kk;
            uint32_t qh0 = Qh[r0 * 36 + c0],       qh1 = Qh[(r0 + 8) * 36 + c0];
            uint32_t qh2 = Qh[r0 * 36 + c0 + 4],   qh3 = Qh[(r0 + 8) * 36 + c0 + 4];
            uint32_t ql0 = Ql[r0 * 36 + c0],       ql1 = Ql[(r0 + 8) * 36 + c0];
            uint32_t ql2 = Ql[r0 * 36 + c0 + 4],   ql3 = Ql[(r0 + 8) * 36 + c0 + 4];
#pragma unroll
            for (int j = 0; j < 8; j++) {
                int key = 8 * j + g;
                uint32_t kh0 = Kh[key * 36 + c0], kh1 = Kh[key * 36 + c0 + 4];
                mma16816(s[j], qh0, qh1, qh2, qh3, kh0, kh1);
                mma16816(s[j], ql0, ql1, ql2, ql3, kh0, kh1);
            }
        }

#pragma unroll
        for (int kk = 0; kk < 4; kk++) {
            uint32_t a0, a1, a2, a3, l0, l1, l2, l3;
            {
                float* sj = s[2 * kk];
                float e0 = __expf(sj[0]), e1 = __expf(sj[1]);
                float e2 = __expf(sj[2]), e3 = __expf(sj[3]);
                rs[0] += e0 + e1; rs[1] += e2 + e3;
                split_pair(e0, e1, a0, l0);
                split_pair(e2, e3, a1, l1);
            }
            {
                float* sj = s[2 * kk + 1];
                float e0 = __expf(sj[0]), e1 = __expf(sj[1]);
                float e2 = __expf(sj[2]), e3 = __expf(sj[3]);
                rs[0] += e0 + e1; rs[1] += e2 + e3;
                split_pair(e0, e1, a2, l2);
                split_pair(e2, e3, a3, l3);
            }
            int cp = qq + 8 * kk;
#pragma unroll
            for (int j = 0; j < 8; j++) {
                int d = 8 * j + g;
                uint32_t vh0 = Vh[d * 36 + cp], vh1 = Vh[d * 36 + cp + 4];
                mma16816(o[j], a0, a1, a2, a3, vh0, vh1);
                mma16816(o[j], l0, l1, l2, l3, vh0, vh1);
            }
        }
        __syncthreads();
    }

    rs[0] += __shfl_xor_sync(0xffffffffu, rs[0], 1);
    rs[0] += __shfl_xor_sync(0xffffffffu, rs[0], 2);
    rs[1] += __shfl_xor_sync(0xffffffffu, rs[1], 1);
    rs[1] += __shfl_xor_sync(0xffffffffu, rs[1], 2);
    float inv0 = 1.0f / rs[0], inv1 = 1.0f / rs[1];

#pragma unroll
    for (int j = 0; j < 8; j++) {
        uint32_t hh, ll;
        size_t r1 = (size_t)(b * NQ + q0 + 16 * w + g) * 256 + h * 32 + 4 * j + qq;
        split_pair(o[j][0] * inv0, o[j][1] * inv0, hh, ll);
        Ah[r1] = hh; Al[r1] = ll;
        split_pair(o[j][2] * inv1, o[j][3] * inv1, hh, ll);
        Ah[r1 + 8 * 256] = hh; Al[r1 + 8 * 256] = ll;
    }
}

// ---------------------------------------------------------------------------
extern "C" void kernel_launch(void* const* d_in, const int* in_sizes, int n_in,
                              void* d_out, int out_size)
{
    const float* x   = (const float*)d_in[0];
    const float* ctx = (const float*)d_in[1];
    const float* Wq  = (const float*)d_in[2];
    const float* Wk  = (const float*)d_in[3];
    const float* Wv  = (const float*)d_in[4];
    const float* Wo  = (const float*)d_in[5];
    const float* bo  = (const float*)d_in[6];
    float* out = (float*)d_out;

    uint32_t *xh, *xl, *ch, *cl, *wqh, *wkh, *wvh, *woh;
    uint32_t *qh, *ql, *kh, *vh, *ah, *al;
    cudaGetSymbolAddress((void**)&xh, g_xh);   cudaGetSymbolAddress((void**)&xl, g_xl);
    cudaGetSymbolAddress((void**)&ch, g_ch);   cudaGetSymbolAddress((void**)&cl, g_cl);
    cudaGetSymbolAddress((void**)&wqh, g_Wqh); cudaGetSymbolAddress((void**)&wkh, g_Wkh);
    cudaGetSymbolAddress((void**)&wvh, g_Wvh); cudaGetSymbolAddress((void**)&woh, g_Woh);
    cudaGetSymbolAddress((void**)&qh, g_Qh);   cudaGetSymbolAddress((void**)&ql, g_Ql);
    cudaGetSymbolAddress((void**)&kh, g_Kh);   cudaGetSymbolAddress((void**)&vh, g_Vh);
    cudaGetSymbolAddress((void**)&ah, g_Ah);   cudaGetSymbolAddress((void**)&al, g_Al);

    cudaFuncSetAttribute(attn_mma3,
                         cudaFuncAttributeMaxDynamicSharedMemorySize, 73728);
    cudaFuncSetAttribute(proj_all,
                         cudaFuncAttributeMaxDynamicSharedMemorySize, 61440);
    cudaFuncSetAttribute(hgemm_out,
                         cudaFuncAttributeMaxDynamicSharedMemorySize, 61440);

    dim3 blk(256);

    convert_all<<<13824, blk>>>(x, ctx, Wq, Wk, Wv, Wo,
                                xh, xl, ch, cl, wqh, wkh, wvh, woh);

    proj_all<<<768, blk, 61440>>>(xh, xl, ch, cl, wqh, wkh, wvh,
                                  qh, ql, kh, vh);

    attn_mma3<<<dim3(NQ / 128, HEADS, BATCH), blk, 73728>>>(
        qh, ql, kh, vh, ah, al);

    hgemm_out<<<dim3(4, (BATCH * NQ) / 128), blk, 61440>>>(
        ah, al, woh, out, INNER, bo);

    (void)in_sizes; (void)n_in; (void)out_size;
}